// round 16
// baseline (speedup 1.0000x reference)
#include <cuda_runtime.h>
#include <cuda_fp16.h>
#include <cstdint>

#define WIDTH 1024
#define HEADS 16
#define ACH   64
#define BS    2
#define NCTX  1024
#define NDATA 4096

#define MQ   (BS*NCTX)     // 2048
#define MKV  (BS*NDATA)    // 8192
#define NKV  (2*WIDTH)     // 2048

// ---------------- scratch (allocation-free rule: __device__ globals) --------
__device__ __half g_xh[MQ*WIDTH];
__device__ __half g_dh[MKV*WIDTH];
__device__ __half g_wqh[WIDTH*WIDTH];                     // [N][K] x1
__device__ __half g_wkvh[NKV*WIDTH];                      // [N][K] x1
__device__ __half g_wph[WIDTH*WIDTH], g_wpl[WIDTH*WIDTH]; // [N][K] h+l
__device__ __half g_qh[MQ*WIDTH];
__device__ __half g_kvh[MKV*NKV];
__device__ __half g_ah[MQ*WIDTH];

// ---------------- helpers -----------------------------------------------------
__device__ __forceinline__ uint32_t smem_u32(const void* p) {
    uint32_t a;
    asm("{ .reg .u64 t; cvta.to.shared.u64 t, %1; cvt.u32.u64 %0, t; }"
        : "=r"(a) : "l"(p));
    return a;
}

__device__ __forceinline__ void cp16(uint32_t dst, const void* src) {
    asm volatile("cp.async.cg.shared.global [%0], [%1], 16;" :: "r"(dst), "l"(src));
}
__device__ __forceinline__ void cp_commit() {
    asm volatile("cp.async.commit_group;" ::: "memory");
}

#define LDMATRIX_X4(r, addr)                                                    \
    asm volatile("ldmatrix.sync.aligned.m8n8.x4.shared.b16 {%0,%1,%2,%3}, [%4];" \
        : "=r"((r)[0]), "=r"((r)[1]), "=r"((r)[2]), "=r"((r)[3]) : "r"(addr))

#define LDMATRIX_X4T(r, addr)                                                   \
    asm volatile("ldmatrix.sync.aligned.m8n8.x4.trans.shared.b16 {%0,%1,%2,%3}, [%4];" \
        : "=r"((r)[0]), "=r"((r)[1]), "=r"((r)[2]), "=r"((r)[3]) : "r"(addr))

#define MMAF16(d, a, b0, b1)                                                    \
    asm volatile("mma.sync.aligned.m16n8k16.row.col.f32.f16.f16.f32 "           \
        "{%0,%1,%2,%3},{%4,%5,%6,%7},{%8,%9},{%0,%1,%2,%3};"                    \
        : "+f"((d)[0]), "+f"((d)[1]), "+f"((d)[2]), "+f"((d)[3])                \
        : "r"((a)[0]), "r"((a)[1]), "r"((a)[2]), "r"((a)[3]), "r"(b0), "r"(b1))

// Round-to-nearest fp16x2 pack (low half = a, high half = b).
__device__ __forceinline__ uint32_t rn_pack2h(float a, float b) {
    uint32_t r;
    asm("cvt.rn.f16x2.f32 %0, %1, %2;" : "=r"(r) : "f"(b), "f"(a));
    return r;
}

// ---------------- conversion kernels ----------------------------------------
__global__ void tohalf_kernel(const float4* __restrict__ src,
                              uint32_t* __restrict__ h, int n4)
{
    int i = blockIdx.x * blockDim.x + threadIdx.x;
    if (i < n4) {
        float4 v = src[i];
        h[i * 2]     = rn_pack2h(v.x, v.y);
        h[i * 2 + 1] = rn_pack2h(v.z, v.w);
    }
}

// W [Kdim][Ndim] fp32 -> Th (RN fp16) and optionally Tl (residual) [Ndim][Kdim]
__global__ void transpose_split_kernel(const float* __restrict__ W,
                                       __half* __restrict__ Th,
                                       __half* __restrict__ Tl,
                                       int Kdim, int Ndim)
{
    __shared__ float tile[32][33];
    int tx = threadIdx.x, ty = threadIdx.y;
    int n0 = blockIdx.x * 32;
    int k0 = blockIdx.y * 32;
#pragma unroll
    for (int i = 0; i < 4; i++) {
        int k = k0 + ty + i * 8;
        tile[ty + i * 8][tx] = W[(size_t)k * Ndim + n0 + tx];
    }
    __syncthreads();
#pragma unroll
    for (int i = 0; i < 4; i++) {
        int n = n0 + ty + i * 8;
        int k = k0 + tx;
        float v = tile[tx][ty + i * 8];
        __half hh = __float2half_rn(v);
        Th[(size_t)n * Kdim + k] = hh;
        if (Tl) Tl[(size_t)n * Kdim + k] = __float2half_rn(v - __half2float(hh));
    }
}

#define GSWZ(off) ((off) ^ (((off) >> 3) & 0x30))

// ---------------- fp16 HMMA GEMM, 128x128 tile (kv) ---------------------------
// C = A[M,K] @ Bh[N,K]^T + bias, fp32 acc, fp16 out. x1 only.
#define TILE_B  (128*64)            // 8192
#define OFF_AH  0
#define OFF_BH  TILE_B
#define STAGE_B (2*TILE_B)          // 16384
#define NSTAGE  3
#define GEMM_SMEM (NSTAGE*STAGE_B)  // 49152

__device__ __forceinline__ void load_stage128(
    uint32_t base, const __half* __restrict__ A, const __half* __restrict__ Bh,
    int K, int bm, int bn, int kc, int tid)
{
    int k0 = kc * 32;
#pragma unroll
    for (int i = 0; i < 2; i++) {
        int idx = tid + i * 256;
        int row = idx >> 2;
        int seg = idx & 3;
        uint32_t off = GSWZ((uint32_t)(row * 64 + seg * 16));
        cp16(base + OFF_AH + off, A + (size_t)(bm + row) * K + k0 + seg * 8);
        cp16(base + OFF_BH + off, Bh + (size_t)(bn + row) * K + k0 + seg * 8);
    }
}

__global__ void __launch_bounds__(256, 2)
gemm_f16_kernel(const __half* __restrict__ A, const __half* __restrict__ Bh,
                const float* __restrict__ bias, __half* __restrict__ Ch,
                int M, int N, int K)
{
    extern __shared__ char smem[];
    const uint32_t sb = smem_u32(smem);

    const int tid  = threadIdx.x;
    const int lane = tid & 31;
    const int wid  = tid >> 5;
    const int warp_m = wid & 3;
    const int warp_n = wid >> 2;
    const int bm = blockIdx.y * 128;
    const int bn = blockIdx.x * 128;

    const int a_row = warp_m * 32 + (lane & 15);
    const int b_row = warp_n * 64 + (lane & 7) + ((lane >> 4) << 3);
    const int a_ch0 = lane >> 4;
    const int b_ch0 = (lane >> 3) & 1;

    float acc[2][8][4];
#pragma unroll
    for (int mi = 0; mi < 2; mi++)
#pragma unroll
        for (int j = 0; j < 8; j++)
#pragma unroll
            for (int r = 0; r < 4; r++) acc[mi][j][r] = 0.0f;

    const int nchunk = K >> 5;

    load_stage128(sb, A, Bh, K, bm, bn, 0, tid);
    cp_commit();
    load_stage128(sb + STAGE_B, A, Bh, K, bm, bn, 1, tid);
    cp_commit();

    int cur = 0, pre = 2;
    for (int kc = 0; kc < nchunk; kc++) {
        asm volatile("cp.async.wait_group 1;" ::: "memory");
        __syncthreads();

        if (kc + 2 < nchunk) {
            load_stage128(sb + (uint32_t)pre * STAGE_B, A, Bh, K, bm, bn, kc + 2, tid);
            cp_commit();
        }

        uint32_t sbase = sb + (uint32_t)cur * STAGE_B;
        cur = (cur + 1 < NSTAGE) ? cur + 1 : 0;
        pre = (pre + 1 < NSTAGE) ? pre + 1 : 0;

#pragma unroll
        for (int ks = 0; ks < 2; ks++) {
            uint32_t ahr[2][4];
#pragma unroll
            for (int mi = 0; mi < 2; mi++) {
                uint32_t ro = (uint32_t)((a_row + mi * 16) * 64);
                uint32_t rx = (ro >> 3) & 0x30;
                uint32_t ao = ro + ((((uint32_t)(a_ch0 + ks * 2)) << 4) ^ rx);
                LDMATRIX_X4(ahr[mi], sbase + OFF_AH + ao);
            }
            uint32_t bhr[4][4];
#pragma unroll
            for (int ni = 0; ni < 4; ni++) {
                uint32_t ro = (uint32_t)((b_row + ni * 16) * 64);
                uint32_t rx = (ro >> 3) & 0x30;
                uint32_t bo = ro + ((((uint32_t)(b_ch0 + ks * 2)) << 4) ^ rx);
                LDMATRIX_X4(bhr[ni], sbase + OFF_BH + bo);
            }
#pragma unroll
            for (int ni = 0; ni < 4; ni++) {
                MMAF16(acc[0][2 * ni],     ahr[0], bhr[ni][0], bhr[ni][1]);
                MMAF16(acc[0][2 * ni + 1], ahr[0], bhr[ni][2], bhr[ni][3]);
                MMAF16(acc[1][2 * ni],     ahr[1], bhr[ni][0], bhr[ni][1]);
                MMAF16(acc[1][2 * ni + 1], ahr[1], bhr[ni][2], bhr[ni][3]);
            }
        }
    }

    const int m_base = bm + warp_m * 32;
    const int n_base = bn + warp_n * 64;
    const int rq = lane >> 2;
    const int cq = (lane & 3) * 2;
#pragma unroll
    for (int mi = 0; mi < 2; mi++) {
#pragma unroll
        for (int j = 0; j < 8; j++) {
            int col = n_base + j * 8 + cq;
            float b0 = bias[col];
            float b1 = bias[col + 1];
            int r0 = m_base + mi * 16 + rq;
            *(uint32_t*)&Ch[(size_t)r0 * N + col] =
                rn_pack2h(acc[mi][j][0] + b0, acc[mi][j][1] + b1);
            *(uint32_t*)&Ch[(size_t)(r0 + 8) * N + col] =
                rn_pack2h(acc[mi][j][2] + b0, acc[mi][j][3] + b1);
        }
    }
}

// ---------------- fp16 HMMA GEMM, 128x64 tile (q / proj) ----------------------
// Grid doubles (256 CTAs for M=2048,N=1024) -> full wave at 2 CTAs/SM.
// mode 0: proj — B x2, fp32 C out.  mode 2: q — B x1, fp16 Ch out.
#define N64_AB   (128*64)            // 8192
#define N64_BB   (64*64)             // 4096
#define N64_OFF_A  0
#define N64_OFF_BH N64_AB
#define N64_OFF_BL (N64_AB + N64_BB)
#define N64_STAGE  (N64_AB + 2*N64_BB)   // 16384
#define N64_NSTAGE 3
#define N64_SMEM   (N64_NSTAGE*N64_STAGE) // 49152

__device__ __forceinline__ void load_stage64(
    uint32_t base, const __half* __restrict__ A,
    const __half* __restrict__ Bh, const __half* __restrict__ Bl,
    int K, int bm, int bn, int kc, int tid, int mode)
{
    int k0 = kc * 32;
#pragma unroll
    for (int i = 0; i < 2; i++) {
        int idx = tid + i * 256;
        int row = idx >> 2;
        int seg = idx & 3;
        uint32_t off = GSWZ((uint32_t)(row * 64 + seg * 16));
        cp16(base + N64_OFF_A + off, A + (size_t)(bm + row) * K + k0 + seg * 8);
    }
    {
        int row = tid >> 2;          // 0..63
        int seg = tid & 3;
        uint32_t off = GSWZ((uint32_t)(row * 64 + seg * 16));
        size_t ge = (size_t)(bn + row) * K + k0 + seg * 8;
        cp16(base + N64_OFF_BH + off, Bh + ge);
        if (mode == 0) cp16(base + N64_OFF_BL + off, Bl + ge);
    }
}

__global__ void __launch_bounds__(256, 2)
gemm_f16_n64_kernel(const __half* __restrict__ A,
                    const __half* __restrict__ Bh, const __half* __restrict__ Bl,
                    const float* __restrict__ bias,
                    float* __restrict__ C, __half* __restrict__ Ch,
                    int M, int N, int K, int mode)
{
    extern __shared__ char smem[];
    const uint32_t sb = smem_u32(smem);

    const int tid  = threadIdx.x;
    const int lane = tid & 31;
    const int wid  = tid >> 5;
    const int warp_m = wid & 3;      // 4 x 32 rows
    const int warp_n = wid >> 2;     // 2 x 32 cols
    const int bm = blockIdx.y * 128;
    const int bn = blockIdx.x * 64;

    const int a_row = warp_m * 32 + (lane & 15);
    const int b_row = warp_n * 32 + (lane & 7) + ((lane >> 4) << 3);
    const int a_ch0 = lane >> 4;
    const int b_ch0 = (lane >> 3) & 1;

    float acc[2][4][4];
#pragma unroll
    for (int mi = 0; mi < 2; mi++)
#pragma unroll
        for (int j = 0; j < 4; j++)
#pragma unroll
            for (int r = 0; r < 4; r++) acc[mi][j][r] = 0.0f;

    const int nchunk = K >> 5;

    load_stage64(sb, A, Bh, Bl, K, bm, bn, 0, tid, mode);
    cp_commit();
    load_stage64(sb + N64_STAGE, A, Bh, Bl, K, bm, bn, 1, tid, mode);
    cp_commit();

    int cur = 0, pre = 2;
    for (int kc = 0; kc < nchunk; kc++) {
        asm volatile("cp.async.wait_group 1;" ::: "memory");
        __syncthreads();

        if (kc + 2 < nchunk) {
            load_stage64(sb + (uint32_t)pre * N64_STAGE, A, Bh, Bl,
                         K, bm, bn, kc + 2, tid, mode);
            cp_commit();
        }

        uint32_t sbase = sb + (uint32_t)cur * N64_STAGE;
        cur = (cur + 1 < N64_NSTAGE) ? cur + 1 : 0;
        pre = (pre + 1 < N64_NSTAGE) ? pre + 1 : 0;

#pragma unroll
        for (int ks = 0; ks < 2; ks++) {
            uint32_t ahr[2][4];
#pragma unroll
            for (int mi = 0; mi < 2; mi++) {
                uint32_t ro = (uint32_t)((a_row + mi * 16) * 64);
                uint32_t rx = (ro >> 3) & 0x30;
                uint32_t ao = ro + ((((uint32_t)(a_ch0 + ks * 2)) << 4) ^ rx);
                LDMATRIX_X4(ahr[mi], sbase + N64_OFF_A + ao);
            }
            uint32_t bhr[2][4];
#pragma unroll
            for (int ni = 0; ni < 2; ni++) {
                uint32_t ro = (uint32_t)((b_row + ni * 16) * 64);
                uint32_t rx = (ro >> 3) & 0x30;
                uint32_t bo = ro + ((((uint32_t)(b_ch0 + ks * 2)) << 4) ^ rx);
                LDMATRIX_X4(bhr[ni], sbase + N64_OFF_BH + bo);
            }
#pragma unroll
            for (int ni = 0; ni < 2; ni++) {
                MMAF16(acc[0][2 * ni],     ahr[0], bhr[ni][0], bhr[ni][1]);
                MMAF16(acc[0][2 * ni + 1], ahr[0], bhr[ni][2], bhr[ni][3]);
                MMAF16(acc[1][2 * ni],     ahr[1], bhr[ni][0], bhr[ni][1]);
                MMAF16(acc[1][2 * ni + 1], ahr[1], bhr[ni][2], bhr[ni][3]);
            }
            if (mode == 0) {
#pragma unroll
                for (int ni = 0; ni < 2; ni++) {
                    uint32_t ro = (uint32_t)((b_row + ni * 16) * 64);
                    uint32_t rx = (ro >> 3) & 0x30;
                    uint32_t bo = ro + ((((uint32_t)(b_ch0 + ks * 2)) << 4) ^ rx);
                    uint32_t blr[4];
                    LDMATRIX_X4(blr, sbase + N64_OFF_BL + bo);
                    MMAF16(acc[0][2 * ni],     ahr[0], blr[0], blr[1]);
                    MMAF16(acc[0][2 * ni + 1], ahr[0], blr[2], blr[3]);
                    MMAF16(acc[1][2 * ni],     ahr[1], blr[0], blr[1]);
                    MMAF16(acc[1][2 * ni + 1], ahr[1], blr[2], blr[3]);
                }
            }
        }
    }

    const int m_base = bm + warp_m * 32;
    const int n_base = bn + warp_n * 32;
    const int rq = lane >> 2;
    const int cq = (lane & 3) * 2;
#pragma unroll
    for (int mi = 0; mi < 2; mi++) {
#pragma unroll
        for (int j = 0; j < 4; j++) {
            int col = n_base + j * 8 + cq;
            float b0 = bias[col];
            float b1 = bias[col + 1];
            int r0 = m_base + mi * 16 + rq;
            float v0 = acc[mi][j][0] + b0, v1 = acc[mi][j][1] + b1;
            float v2 = acc[mi][j][2] + b0, v3 = acc[mi][j][3] + b1;
            if (mode == 0) {
                *(float2*)&C[(size_t)r0 * N + col]       = make_float2(v0, v1);
                *(float2*)&C[(size_t)(r0 + 8) * N + col] = make_float2(v2, v3);
            } else {
                *(uint32_t*)&Ch[(size_t)r0 * N + col]       = rn_pack2h(v0, v1);
                *(uint32_t*)&Ch[(size_t)(r0 + 8) * N + col] = rn_pack2h(v2, v3);
            }
        }
    }
}

// ---------------- fp16 HMMA flash attention -------------------------------------
// 128 query rows per CTA for one (b,h). 8 warps x m16.
// QK^T x1, PV x1, no online max; l reduced once post-loop.
// 3-stage (K,V) ring, 1 sync per chunk, 2 CTAs/SM.
#define APITCH 144
#define AQH 0
#define AST (128*APITCH)                 // 18432 (Q region)
#define TKH 0
#define TVH (64*APITCH)                  // 9216
#define ASTAGE (128*APITCH)              // 18432 (K + V)
#define ANSTAGE 3
#define ATTN_SMEM (AST + ANSTAGE*ASTAGE) // 73728

__device__ __forceinline__ void load_kv_stage(uint32_t dst, int b, int h, int s0, int tid)
{
#pragma unroll
    for (int i = 0; i < 2; i++) {
        int idx = tid + i * 256;
        int row = idx >> 3;
        int seg = idx & 7;
        size_t base = (size_t)(b * NDATA + s0 + row) * NKV + h * 128 + seg * 8;
        uint32_t so = (uint32_t)(row * APITCH + seg * 16);
        cp16(dst + TKH + so, g_kvh + base);          // K
        cp16(dst + TVH + so, g_kvh + base + 64);     // V
    }
}

__global__ void __launch_bounds__(256, 2)
attn_hmma_kernel()
{
    extern __shared__ char smem[];
    const uint32_t sb = smem_u32(smem);

    const int tid  = threadIdx.x;
    const int lane = tid & 31;
    const int wid  = tid >> 5;
    const int qt = blockIdx.x;
    const int h  = blockIdx.y;
    const int b  = blockIdx.z;
    const int t0 = qt * 128;

    // group 1: Q tile
#pragma unroll
    for (int i = 0; i < 4; i++) {
        int idx = tid + i * 256;
        int row = idx >> 3;
        int seg = idx & 7;
        size_t go = (size_t)(b * NCTX + t0 + row) * WIDTH + h * ACH + seg * 8;
        cp16(sb + AQH + (uint32_t)(row * APITCH + seg * 16), g_qh + go);
    }
    cp_commit();
    load_kv_stage(sb + AST, b, h, 0, tid);
    cp_commit();
    load_kv_stage(sb + AST + ASTAGE, b, h, 64, tid);
    cp_commit();

    asm volatile("cp.async.wait_group 2;" ::: "memory");
    __syncthreads();
    uint32_t qhf[4][4];
    {
        uint32_t qa = (uint32_t)((wid * 16 + (lane & 15)) * APITCH + ((lane >> 4) << 4));
#pragma unroll
        for (int kc = 0; kc < 4; kc++)
            LDMATRIX_X4(qhf[kc], sb + AQH + qa + kc * 32);
    }

    const uint32_t kb = (uint32_t)(((lane & 7) + ((lane >> 4) << 3)) * APITCH
                                   + (((lane >> 3) & 1) << 4));
    const uint32_t vb = (uint32_t)((lane & 15) * APITCH + ((lane >> 4) << 4));

    float l0 = 0.0f, l1 = 0.0f;
    float o[8][4];
#pragma unroll
    for (int j = 0; j < 8; j++)
#pragma unroll
        for (int e = 0; e < 4; e++) o[j][e] = 0.0f;

    const float CS = 0.125f * 1.44269504f;

    int cur = 0;
    int pre = 2;

    const int NCHUNK = NDATA / 64;    // 64
    for (int sc = 0; sc < NCHUNK; sc++) {
        asm volatile("cp.async.wait_group 1;" ::: "memory");
        __syncthreads();

        if (sc + 2 < NCHUNK) {
            load_kv_stage(sb + AST + (uint32_t)pre * ASTAGE,
                          b, h, (sc + 2) * 64, tid);
            cp_commit();
        }

        uint32_t st = sb + AST + (uint32_t)cur * ASTAGE;
        cur = (cur + 1 < ANSTAGE) ? cur + 1 : 0;
        pre = (pre + 1 < ANSTAGE) ? pre + 1 : 0;

        // ---- S = Q K^T ----
        float sacc[8][4];
#pragma unroll
        for (int j = 0; j < 8; j++)
#pragma unroll
            for (int e = 0; e < 4; e++) sacc[j][e] = 0.0f;

#pragma unroll
        for (int kc = 0; kc < 4; kc++) {
            uint32_t khf[4][4];
#pragma unroll
            for (int g = 0; g < 4; g++)
                LDMATRIX_X4(khf[g], st + TKH + kb + (uint32_t)(g * 16 * APITCH) + kc * 32);
#pragma unroll
            for (int g = 0; g < 4; g++) {
                MMAF16(sacc[2 * g],     qhf[kc], khf[g][0], khf[g][1]);
                MMAF16(sacc[2 * g + 1], qhf[kc], khf[g][2], khf[g][3]);
            }
        }

        // ---- softmax numerator: p = exp2(s*CS), fixed shift 0 ----
#pragma unroll
        for (int j = 0; j < 8; j++) {
            float p0 = exp2f(sacc[j][0] * CS);
            float p1 = exp2f(sacc[j][1] * CS);
            float p2 = exp2f(sacc[j][2] * CS);
            float p3 = exp2f(sacc[j][3] * CS);
            sacc[j][0] = p0; sacc[j][1] = p1; sacc[j][2] = p2; sacc[j][3] = p3;
            l0 += p0 + p1;
            l1 += p2 + p3;
        }

        // ---- pack P into A fragments (RN fp16) ----
        uint32_t ph[4][4];
#pragma unroll
        for (int kc = 0; kc < 4; kc++) {
            int j0 = 2 * kc, j1 = 2 * kc + 1;
            ph[kc][0] = rn_pack2h(sacc[j0][0], sacc[j0][1]);
            ph[kc][1] = rn_pack2h(sacc[j0][2], sacc[j0][3]);
            ph[kc][2] = rn_pack2h(sacc[j1][0], sacc[j1][1]);
            ph[kc][3] = rn_pack2h(sacc[j1][2], sacc[j1][3]);
        }

        // ---- O += P V (x1) ----
#pragma unroll
        for (int kc = 0; kc < 4; kc++) {
#pragma unroll
            for (int gp = 0; gp < 2; gp++) {
                int g0 = gp * 2, g1 = gp * 2 + 1;
                uint32_t vh0[4], vh1[4];
                LDMATRIX_X4T(vh0, st + TVH + vb + (uint32_t)(kc * 16 * APITCH) + g0 * 32);
                LDMATRIX_X4T(vh1, st + TVH + vb + (uint32_t)(kc * 16 * APITCH) + g1 * 32);
                MMAF16(o[2 * g0],     ph[kc], vh0[0], vh0[1]);
                MMAF16(o[2 * g0 + 1], ph[kc], vh0[2], vh0[3]);
                MMAF16(o[2 * g1],     ph[kc], vh1[0], vh1[1]);
                MMAF16(o[2 * g1 + 1], ph[kc], vh1[2], vh1[3]);
            }
        }
    }

    // ---- one deferred row-sum reduction ----
    l0 += __shfl_xor_sync(0xffffffffu, l0, 1);
    l0 += __shfl_xor_sync(0xffffffffu, l0, 2);
    l1 += __shfl_xor_sync(0xffffffffu, l1, 1);
    l1 += __shfl_xor_sync(0xffffffffu, l1, 2);

    // ---- epilogue: normalize, RN fp16, store ----
    float inv0 = 1.0f / l0;
    float inv1 = 1.0f / l1;
    int r = t0 + wid * 16 + (lane >> 2);
    int cq = (lane & 3) * 2;
#pragma unroll
    for (int j = 0; j < 8; j++) {
        int col = h * ACH + j * 8 + cq;
        *(uint32_t*)&g_ah[(size_t)(b * NCTX + r) * WIDTH + col] =
            rn_pack2h(o[j][0] * inv0, o[j][1] * inv0);
        *(uint32_t*)&g_ah[(size_t)(b * NCTX + r + 8) * WIDTH + col] =
            rn_pack2h(o[j][2] * inv1, o[j][3] * inv1);
    }
}

// ---------------- launch ------------------------------------------------------
extern "C" void kernel_launch(void* const* d_in, const int* in_sizes, int n_in,
                              void* d_out, int out_size)
{
    (void)in_sizes; (void)n_in; (void)out_size;

    const float* x     = (const float*)d_in[0];
    const float* data  = (const float*)d_in[1];
    const float* Wq    = (const float*)d_in[2];
    const float* bq    = (const float*)d_in[3];
    const float* Wkv   = (const float*)d_in[4];
    const float* bkv   = (const float*)d_in[5];
    const float* Wproj = (const float*)d_in[6];
    const float* bproj = (const float*)d_in[7];
    float* out = (float*)d_out;

    __half *xh, *dh, *wqh, *wkvh, *wph, *wpl, *qh, *kvh, *ah;
    cudaGetSymbolAddress((void**)&xh,  g_xh);
    cudaGetSymbolAddress((void**)&dh,  g_dh);
    cudaGetSymbolAddress((void**)&wqh, g_wqh);
    cudaGetSymbolAddress((void**)&wkvh,g_wkvh);
    cudaGetSymbolAddress((void**)&wph, g_wph);  cudaGetSymbolAddress((void**)&wpl, g_wpl);
    cudaGetSymbolAddress((void**)&qh,  g_qh);
    cudaGetSymbolAddress((void**)&kvh, g_kvh);
    cudaGetSymbolAddress((void**)&ah,  g_ah);

    // One-time setup (first call is the un-captured correctness run).
    static cudaStream_t s1 = nullptr;
    static cudaEvent_t ev_fork = nullptr, ev_join = nullptr;
    if (s1 == nullptr) {
        cudaStreamCreateWithFlags(&s1, cudaStreamNonBlocking);
        cudaEventCreateWithFlags(&ev_fork, cudaEventDisableTiming);
        cudaEventCreateWithFlags(&ev_join, cudaEventDisableTiming);
        cudaFuncSetAttribute(gemm_f16_kernel,
                             cudaFuncAttributeMaxDynamicSharedMemorySize, GEMM_SMEM);
        cudaFuncSetAttribute(gemm_f16_n64_kernel,
                             cudaFuncAttributeMaxDynamicSharedMemorySize, N64_SMEM);
        cudaFuncSetAttribute(attn_hmma_kernel,
                             cudaFuncAttributeMaxDynamicSharedMemorySize, ATTN_SMEM);
    }

    // ---- fork: q-path on s1, kv-path on capture (default) stream ----
    cudaEventRecord(ev_fork, 0);
    cudaStreamWaitEvent(s1, ev_fork, 0);

    // q-path (s1): x->fp16, transpose Wq (x1), q GEMM (n64, x1); also Wproj h+l.
    tohalf_kernel<<<(MQ * WIDTH / 4 + 255) / 256, 256, 0, s1>>>(
        (const float4*)x, (uint32_t*)xh, MQ * WIDTH / 4);
    {
        dim3 blk(32, 8);
        transpose_split_kernel<<<dim3(WIDTH / 32, WIDTH / 32), blk, 0, s1>>>(
            Wq, wqh, nullptr, WIDTH, WIDTH);
        transpose_split_kernel<<<dim3(WIDTH / 32, WIDTH / 32), blk, 0, s1>>>(
            Wproj, wph, wpl, WIDTH, WIDTH);
    }
    gemm_f16_n64_kernel<<<dim3(WIDTH / 64, MQ / 128), 256, N64_SMEM, s1>>>(
        xh, wqh, nullptr, bq, nullptr, qh, MQ, WIDTH, WIDTH, 2);

    // kv-path (default stream): data->fp16, transpose Wkv (x1), kv GEMM (128, x1).
    tohalf_kernel<<<(MKV * WIDTH / 4 + 255) / 256, 256>>>(
        (const float4*)data, (uint32_t*)dh, MKV * WIDTH / 4);
    {
        dim3 blk(32, 8);
        transpose_split_kernel<<<dim3(NKV / 32, WIDTH / 32), blk>>>(
            Wkv, wkvh, nullptr, WIDTH, NKV);
    }
    gemm_f16_kernel<<<dim3(NKV / 128, MKV / 128), 256, GEMM_SMEM>>>(
        dh, wkvh, bkv, kvh, MKV, NKV, WIDTH);

    // ---- join: attention needs both q and kv ----
    cudaEventRecord(ev_join, s1);
    cudaStreamWaitEvent(0, ev_join, 0);

    // attention -> fp16 output
    attn_hmma_kernel<<<dim3(NCTX / 128, HEADS, BS), 256, ATTN_SMEM>>>();

    // out = attn @ Wproj + bproj  (n64, B x2, fp32 output)
    gemm_f16_n64_kernel<<<dim3(WIDTH / 64, MQ / 128), 256, N64_SMEM>>>(
        ah, wph, wpl, bproj, out, nullptr, MQ, WIDTH, WIDTH, 0);
}

// round 17
// speedup vs baseline: 1.0804x; 1.0804x over previous
#include <cuda_runtime.h>
#include <cuda_fp16.h>
#include <cstdint>

#define WIDTH 1024
#define HEADS 16
#define ACH   64
#define BS    2
#define NCTX  1024
#define NDATA 4096

#define MQ   (BS*NCTX)     // 2048
#define MKV  (BS*NDATA)    // 8192
#define NKV  (2*WIDTH)     // 2048

// ---------------- scratch (allocation-free rule: __device__ globals) --------
__device__ __half g_xh[MQ*WIDTH];
__device__ __half g_dh[MKV*WIDTH];
__device__ __half g_wqh[WIDTH*WIDTH];     // [N][K] x1
__device__ __half g_wkvh[NKV*WIDTH];      // [N][K] x1
__device__ __half g_wph[WIDTH*WIDTH];     // [N][K] x1
__device__ __half g_qh[MQ*WIDTH];
__device__ __half g_kvh[MKV*NKV];
__device__ __half g_ah[MQ*WIDTH];

// ---------------- helpers -----------------------------------------------------
__device__ __forceinline__ uint32_t smem_u32(const void* p) {
    uint32_t a;
    asm("{ .reg .u64 t; cvta.to.shared.u64 t, %1; cvt.u32.u64 %0, t; }"
        : "=r"(a) : "l"(p));
    return a;
}

__device__ __forceinline__ void cp16(uint32_t dst, const void* src) {
    asm volatile("cp.async.cg.shared.global [%0], [%1], 16;" :: "r"(dst), "l"(src));
}
__device__ __forceinline__ void cp_commit() {
    asm volatile("cp.async.commit_group;" ::: "memory");
}

#define LDMATRIX_X4(r, addr)                                                    \
    asm volatile("ldmatrix.sync.aligned.m8n8.x4.shared.b16 {%0,%1,%2,%3}, [%4];" \
        : "=r"((r)[0]), "=r"((r)[1]), "=r"((r)[2]), "=r"((r)[3]) : "r"(addr))

#define LDMATRIX_X4T(r, addr)                                                   \
    asm volatile("ldmatrix.sync.aligned.m8n8.x4.trans.shared.b16 {%0,%1,%2,%3}, [%4];" \
        : "=r"((r)[0]), "=r"((r)[1]), "=r"((r)[2]), "=r"((r)[3]) : "r"(addr))

#define MMAF16(d, a, b0, b1)                                                    \
    asm volatile("mma.sync.aligned.m16n8k16.row.col.f32.f16.f16.f32 "           \
        "{%0,%1,%2,%3},{%4,%5,%6,%7},{%8,%9},{%0,%1,%2,%3};"                    \
        : "+f"((d)[0]), "+f"((d)[1]), "+f"((d)[2]), "+f"((d)[3])                \
        : "r"((a)[0]), "r"((a)[1]), "r"((a)[2]), "r"((a)[3]), "r"(b0), "r"(b1))

// Round-to-nearest fp16x2 pack (low half = a, high half = b).
__device__ __forceinline__ uint32_t rn_pack2h(float a, float b) {
    uint32_t r;
    asm("cvt.rn.f16x2.f32 %0, %1, %2;" : "=r"(r) : "f"(b), "f"(a));
    return r;
}

// ---------------- conversion kernels ----------------------------------------
__global__ void tohalf_kernel(const float4* __restrict__ src,
                              uint32_t* __restrict__ h, int n4)
{
    int i = blockIdx.x * blockDim.x + threadIdx.x;
    if (i < n4) {
        float4 v = src[i];
        h[i * 2]     = rn_pack2h(v.x, v.y);
        h[i * 2 + 1] = rn_pack2h(v.z, v.w);
    }
}

// W [Kdim][Ndim] fp32 -> Th (RN fp16) [Ndim][Kdim]
__global__ void transpose_half_kernel(const float* __restrict__ W,
                                      __half* __restrict__ Th,
                                      int Kdim, int Ndim)
{
    __shared__ float tile[32][33];
    int tx = threadIdx.x, ty = threadIdx.y;
    int n0 = blockIdx.x * 32;
    int k0 = blockIdx.y * 32;
#pragma unroll
    for (int i = 0; i < 4; i++) {
        int k = k0 + ty + i * 8;
        tile[ty + i * 8][tx] = W[(size_t)k * Ndim + n0 + tx];
    }
    __syncthreads();
#pragma unroll
    for (int i = 0; i < 4; i++) {
        int n = n0 + ty + i * 8;
        int k = k0 + tx;
        Th[(size_t)n * Kdim + k] = __float2half_rn(tile[tx][ty + i * 8]);
    }
}

#define GSWZ(off) ((off) ^ (((off) >> 3) & 0x30))

// ---------------- fp16 HMMA GEMM, 128x128 tile, x1 ----------------------------
// C = A[M,K] @ Bh[N,K]^T + bias, fp32 acc.
// out_fp32: fp32 C, else RN fp16 Ch. Front-loaded LDSM, 3-stage ring, 2 CTAs/SM.
#define TILE_B  (128*64)            // 8192
#define OFF_AH  0
#define OFF_BH  TILE_B
#define STAGE_B (2*TILE_B)          // 16384
#define NSTAGE  3
#define GEMM_SMEM (NSTAGE*STAGE_B)  // 49152

__device__ __forceinline__ void load_stage128(
    uint32_t base, const __half* __restrict__ A, const __half* __restrict__ Bh,
    int K, int bm, int bn, int kc, int tid)
{
    int k0 = kc * 32;
#pragma unroll
    for (int i = 0; i < 2; i++) {
        int idx = tid + i * 256;
        int row = idx >> 2;
        int seg = idx & 3;
        uint32_t off = GSWZ((uint32_t)(row * 64 + seg * 16));
        cp16(base + OFF_AH + off, A + (size_t)(bm + row) * K + k0 + seg * 8);
        cp16(base + OFF_BH + off, Bh + (size_t)(bn + row) * K + k0 + seg * 8);
    }
}

__global__ void __launch_bounds__(256, 2)
gemm_f16_kernel(const __half* __restrict__ A, const __half* __restrict__ Bh,
                const float* __restrict__ bias,
                float* __restrict__ C, __half* __restrict__ Ch,
                int M, int N, int K, int out_fp32)
{
    extern __shared__ char smem[];
    const uint32_t sb = smem_u32(smem);

    const int tid  = threadIdx.x;
    const int lane = tid & 31;
    const int wid  = tid >> 5;
    const int warp_m = wid & 3;
    const int warp_n = wid >> 2;
    const int bm = blockIdx.y * 128;
    const int bn = blockIdx.x * 128;

    const int a_row = warp_m * 32 + (lane & 15);
    const int b_row = warp_n * 64 + (lane & 7) + ((lane >> 4) << 3);
    const int a_ch0 = lane >> 4;
    const int b_ch0 = (lane >> 3) & 1;

    float acc[2][8][4];
#pragma unroll
    for (int mi = 0; mi < 2; mi++)
#pragma unroll
        for (int j = 0; j < 8; j++)
#pragma unroll
            for (int r = 0; r < 4; r++) acc[mi][j][r] = 0.0f;

    const int nchunk = K >> 5;

    load_stage128(sb, A, Bh, K, bm, bn, 0, tid);
    cp_commit();
    load_stage128(sb + STAGE_B, A, Bh, K, bm, bn, 1, tid);
    cp_commit();

    int cur = 0, pre = 2;
    for (int kc = 0; kc < nchunk; kc++) {
        asm volatile("cp.async.wait_group 1;" ::: "memory");
        __syncthreads();

        if (kc + 2 < nchunk) {
            load_stage128(sb + (uint32_t)pre * STAGE_B, A, Bh, K, bm, bn, kc + 2, tid);
            cp_commit();
        }

        uint32_t sbase = sb + (uint32_t)cur * STAGE_B;
        cur = (cur + 1 < NSTAGE) ? cur + 1 : 0;
        pre = (pre + 1 < NSTAGE) ? pre + 1 : 0;

#pragma unroll
        for (int ks = 0; ks < 2; ks++) {
            uint32_t ahr[2][4];
#pragma unroll
            for (int mi = 0; mi < 2; mi++) {
                uint32_t ro = (uint32_t)((a_row + mi * 16) * 64);
                uint32_t rx = (ro >> 3) & 0x30;
                uint32_t ao = ro + ((((uint32_t)(a_ch0 + ks * 2)) << 4) ^ rx);
                LDMATRIX_X4(ahr[mi], sbase + OFF_AH + ao);
            }
            uint32_t bhr[4][4];
#pragma unroll
            for (int ni = 0; ni < 4; ni++) {
                uint32_t ro = (uint32_t)((b_row + ni * 16) * 64);
                uint32_t rx = (ro >> 3) & 0x30;
                uint32_t bo = ro + ((((uint32_t)(b_ch0 + ks * 2)) << 4) ^ rx);
                LDMATRIX_X4(bhr[ni], sbase + OFF_BH + bo);
            }
#pragma unroll
            for (int ni = 0; ni < 4; ni++) {
                MMAF16(acc[0][2 * ni],     ahr[0], bhr[ni][0], bhr[ni][1]);
                MMAF16(acc[0][2 * ni + 1], ahr[0], bhr[ni][2], bhr[ni][3]);
                MMAF16(acc[1][2 * ni],     ahr[1], bhr[ni][0], bhr[ni][1]);
                MMAF16(acc[1][2 * ni + 1], ahr[1], bhr[ni][2], bhr[ni][3]);
            }
        }
    }

    const int m_base = bm + warp_m * 32;
    const int n_base = bn + warp_n * 64;
    const int rq = lane >> 2;
    const int cq = (lane & 3) * 2;
#pragma unroll
    for (int mi = 0; mi < 2; mi++) {
#pragma unroll
        for (int j = 0; j < 8; j++) {
            int col = n_base + j * 8 + cq;
            float b0 = bias[col];
            float b1 = bias[col + 1];
            int r0 = m_base + mi * 16 + rq;
            float v0 = acc[mi][j][0] + b0, v1 = acc[mi][j][1] + b1;
            float v2 = acc[mi][j][2] + b0, v3 = acc[mi][j][3] + b1;
            if (out_fp32) {
                *(float2*)&C[(size_t)r0 * N + col]       = make_float2(v0, v1);
                *(float2*)&C[(size_t)(r0 + 8) * N + col] = make_float2(v2, v3);
            } else {
                *(uint32_t*)&Ch[(size_t)r0 * N + col]       = rn_pack2h(v0, v1);
                *(uint32_t*)&Ch[(size_t)(r0 + 8) * N + col] = rn_pack2h(v2, v3);
            }
        }
    }
}

// ---------------- fp16 HMMA flash attention -------------------------------------
// 128 query rows per CTA for one (b,h). 8 warps x m16.
// QK^T x1, PV x1, no online max; l reduced once post-loop.
// 3-stage (K,V) ring, 1 sync per chunk, 2 CTAs/SM.
#define APITCH 144
#define AQH 0
#define AST (128*APITCH)                 // 18432 (Q region)
#define TKH 0
#define TVH (64*APITCH)                  // 9216
#define ASTAGE (128*APITCH)              // 18432 (K + V)
#define ANSTAGE 3
#define ATTN_SMEM (AST + ANSTAGE*ASTAGE) // 73728

__device__ __forceinline__ void load_kv_stage(uint32_t dst, int b, int h, int s0, int tid)
{
#pragma unroll
    for (int i = 0; i < 2; i++) {
        int idx = tid + i * 256;
        int row = idx >> 3;
        int seg = idx & 7;
        size_t base = (size_t)(b * NDATA + s0 + row) * NKV + h * 128 + seg * 8;
        uint32_t so = (uint32_t)(row * APITCH + seg * 16);
        cp16(dst + TKH + so, g_kvh + base);          // K
        cp16(dst + TVH + so, g_kvh + base + 64);     // V
    }
}

__global__ void __launch_bounds__(256, 2)
attn_hmma_kernel()
{
    extern __shared__ char smem[];
    const uint32_t sb = smem_u32(smem);

    const int tid  = threadIdx.x;
    const int lane = tid & 31;
    const int wid  = tid >> 5;
    const int qt = blockIdx.x;
    const int h  = blockIdx.y;
    const int b  = blockIdx.z;
    const int t0 = qt * 128;

    // group 1: Q tile
#pragma unroll
    for (int i = 0; i < 4; i++) {
        int idx = tid + i * 256;
        int row = idx >> 3;
        int seg = idx & 7;
        size_t go = (size_t)(b * NCTX + t0 + row) * WIDTH + h * ACH + seg * 8;
        cp16(sb + AQH + (uint32_t)(row * APITCH + seg * 16), g_qh + go);
    }
    cp_commit();
    load_kv_stage(sb + AST, b, h, 0, tid);
    cp_commit();
    load_kv_stage(sb + AST + ASTAGE, b, h, 64, tid);
    cp_commit();

    asm volatile("cp.async.wait_group 2;" ::: "memory");
    __syncthreads();
    uint32_t qhf[4][4];
    {
        uint32_t qa = (uint32_t)((wid * 16 + (lane & 15)) * APITCH + ((lane >> 4) << 4));
#pragma unroll
        for (int kc = 0; kc < 4; kc++)
            LDMATRIX_X4(qhf[kc], sb + AQH + qa + kc * 32);
    }

    const uint32_t kb = (uint32_t)(((lane & 7) + ((lane >> 4) << 3)) * APITCH
                                   + (((lane >> 3) & 1) << 4));
    const uint32_t vb = (uint32_t)((lane & 15) * APITCH + ((lane >> 4) << 4));

    float l0 = 0.0f, l1 = 0.0f;
    float o[8][4];
#pragma unroll
    for (int j = 0; j < 8; j++)
#pragma unroll
        for (int e = 0; e < 4; e++) o[j][e] = 0.0f;

    const float CS = 0.125f * 1.44269504f;

    int cur = 0;
    int pre = 2;

    const int NCHUNK = NDATA / 64;    // 64
    for (int sc = 0; sc < NCHUNK; sc++) {
        asm volatile("cp.async.wait_group 1;" ::: "memory");
        __syncthreads();

        if (sc + 2 < NCHUNK) {
            load_kv_stage(sb + AST + (uint32_t)pre * ASTAGE,
                          b, h, (sc + 2) * 64, tid);
            cp_commit();
        }

        uint32_t st = sb + AST + (uint32_t)cur * ASTAGE;
        cur = (cur + 1 < ANSTAGE) ? cur + 1 : 0;
        pre = (pre + 1 < ANSTAGE) ? pre + 1 : 0;

        // ---- S = Q K^T ----
        float sacc[8][4];
#pragma unroll
        for (int j = 0; j < 8; j++)
#pragma unroll
            for (int e = 0; e < 4; e++) sacc[j][e] = 0.0f;

#pragma unroll
        for (int kc = 0; kc < 4; kc++) {
            uint32_t khf[4][4];
#pragma unroll
            for (int g = 0; g < 4; g++)
                LDMATRIX_X4(khf[g], st + TKH + kb + (uint32_t)(g * 16 * APITCH) + kc * 32);
#pragma unroll
            for (int g = 0; g < 4; g++) {
                MMAF16(sacc[2 * g],     qhf[kc], khf[g][0], khf[g][1]);
                MMAF16(sacc[2 * g + 1], qhf[kc], khf[g][2], khf[g][3]);
            }
        }

        // ---- softmax numerator: p = exp2(s*CS), fixed shift 0 ----
#pragma unroll
        for (int j = 0; j < 8; j++) {
            float p0 = exp2f(sacc[j][0] * CS);
            float p1 = exp2f(sacc[j][1] * CS);
            float p2 = exp2f(sacc[j][2] * CS);
            float p3 = exp2f(sacc[j][3] * CS);
            sacc[j][0] = p0; sacc[j][1] = p1; sacc[j][2] = p2; sacc[j][3] = p3;
            l0 += p0 + p1;
            l1 += p2 + p3;
        }

        // ---- pack P into A fragments (RN fp16) ----
        uint32_t ph[4][4];
#pragma unroll
        for (int kc = 0; kc < 4; kc++) {
            int j0 = 2 * kc, j1 = 2 * kc + 1;
            ph[kc][0] = rn_pack2h(sacc[j0][0], sacc[j0][1]);
            ph[kc][1] = rn_pack2h(sacc[j0][2], sacc[j0][3]);
            ph[kc][2] = rn_pack2h(sacc[j1][0], sacc[j1][1]);
            ph[kc][3] = rn_pack2h(sacc[j1][2], sacc[j1][3]);
        }

        // ---- O += P V (x1) ----
#pragma unroll
        for (int kc = 0; kc < 4; kc++) {
#pragma unroll
            for (int gp = 0; gp < 2; gp++) {
                int g0 = gp * 2, g1 = gp * 2 + 1;
                uint32_t vh0[4], vh1[4];
                LDMATRIX_X4T(vh0, st + TVH + vb + (uint32_t)(kc * 16 * APITCH) + g0 * 32);
                LDMATRIX_X4T(vh1, st + TVH + vb + (uint32_t)(kc * 16 * APITCH) + g1 * 32);
                MMAF16(o[2 * g0],     ph[kc], vh0[0], vh0[1]);
                MMAF16(o[2 * g0 + 1], ph[kc], vh0[2], vh0[3]);
                MMAF16(o[2 * g1],     ph[kc], vh1[0], vh1[1]);
                MMAF16(o[2 * g1 + 1], ph[kc], vh1[2], vh1[3]);
            }
        }
    }

    // ---- one deferred row-sum reduction ----
    l0 += __shfl_xor_sync(0xffffffffu, l0, 1);
    l0 += __shfl_xor_sync(0xffffffffu, l0, 2);
    l1 += __shfl_xor_sync(0xffffffffu, l1, 1);
    l1 += __shfl_xor_sync(0xffffffffu, l1, 2);

    // ---- epilogue: normalize, RN fp16, store ----
    float inv0 = 1.0f / l0;
    float inv1 = 1.0f / l1;
    int r = t0 + wid * 16 + (lane >> 2);
    int cq = (lane & 3) * 2;
#pragma unroll
    for (int j = 0; j < 8; j++) {
        int col = h * ACH + j * 8 + cq;
        *(uint32_t*)&g_ah[(size_t)(b * NCTX + r) * WIDTH + col] =
            rn_pack2h(o[j][0] * inv0, o[j][1] * inv0);
        *(uint32_t*)&g_ah[(size_t)(b * NCTX + r + 8) * WIDTH + col] =
            rn_pack2h(o[j][2] * inv1, o[j][3] * inv1);
    }
}

// ---------------- launch ------------------------------------------------------
extern "C" void kernel_launch(void* const* d_in, const int* in_sizes, int n_in,
                              void* d_out, int out_size)
{
    (void)in_sizes; (void)n_in; (void)out_size;

    const float* x     = (const float*)d_in[0];
    const float* data  = (const float*)d_in[1];
    const float* Wq    = (const float*)d_in[2];
    const float* bq    = (const float*)d_in[3];
    const float* Wkv   = (const float*)d_in[4];
    const float* bkv   = (const float*)d_in[5];
    const float* Wproj = (const float*)d_in[6];
    const float* bproj = (const float*)d_in[7];
    float* out = (float*)d_out;

    __half *xh, *dh, *wqh, *wkvh, *wph, *qh, *kvh, *ah;
    cudaGetSymbolAddress((void**)&xh,  g_xh);
    cudaGetSymbolAddress((void**)&dh,  g_dh);
    cudaGetSymbolAddress((void**)&wqh, g_wqh);
    cudaGetSymbolAddress((void**)&wkvh,g_wkvh);
    cudaGetSymbolAddress((void**)&wph, g_wph);
    cudaGetSymbolAddress((void**)&qh,  g_qh);
    cudaGetSymbolAddress((void**)&kvh, g_kvh);
    cudaGetSymbolAddress((void**)&ah,  g_ah);

    // One-time setup (first call is the un-captured correctness run).
    static cudaStream_t s1 = nullptr;
    static cudaEvent_t ev_fork = nullptr, ev_join = nullptr;
    if (s1 == nullptr) {
        cudaStreamCreateWithFlags(&s1, cudaStreamNonBlocking);
        cudaEventCreateWithFlags(&ev_fork, cudaEventDisableTiming);
        cudaEventCreateWithFlags(&ev_join, cudaEventDisableTiming);
        cudaFuncSetAttribute(gemm_f16_kernel,
                             cudaFuncAttributeMaxDynamicSharedMemorySize, GEMM_SMEM);
        cudaFuncSetAttribute(attn_hmma_kernel,
                             cudaFuncAttributeMaxDynamicSharedMemorySize, ATTN_SMEM);
    }

    // ---- fork: q-path on s1, kv-path on capture (default) stream ----
    cudaEventRecord(ev_fork, 0);
    cudaStreamWaitEvent(s1, ev_fork, 0);

    // q-path (s1): x->fp16, transpose Wq, q GEMM; also Wproj transpose.
    tohalf_kernel<<<(MQ * WIDTH / 4 + 255) / 256, 256, 0, s1>>>(
        (const float4*)x, (uint32_t*)xh, MQ * WIDTH / 4);
    {
        dim3 blk(32, 8);
        transpose_half_kernel<<<dim3(WIDTH / 32, WIDTH / 32), blk, 0, s1>>>(
            Wq, wqh, WIDTH, WIDTH);
        transpose_half_kernel<<<dim3(WIDTH / 32, WIDTH / 32), blk, 0, s1>>>(
            Wproj, wph, WIDTH, WIDTH);
    }
    gemm_f16_kernel<<<dim3(WIDTH / 128, MQ / 128), 256, GEMM_SMEM, s1>>>(
        xh, wqh, bq, nullptr, qh, MQ, WIDTH, WIDTH, 0);

    // kv-path (default stream): data->fp16, transpose Wkv, kv GEMM.
    tohalf_kernel<<<(MKV * WIDTH / 4 + 255) / 256, 256>>>(
        (const float4*)data, (uint32_t*)dh, MKV * WIDTH / 4);
    {
        dim3 blk(32, 8);
        transpose_half_kernel<<<dim3(NKV / 32, WIDTH / 32), blk>>>(
            Wkv, wkvh, WIDTH, NKV);
    }
    gemm_f16_kernel<<<dim3(NKV / 128, MKV / 128), 256, GEMM_SMEM>>>(
        dh, wkvh, bkv, nullptr, kvh, MKV, NKV, WIDTH, 0);

    // ---- join: attention needs both q and kv ----
    cudaEventRecord(ev_join, s1);
    cudaStreamWaitEvent(0, ev_join, 0);

    // attention -> fp16 output
    attn_hmma_kernel<<<dim3(NCTX / 128, HEADS, BS), 256, ATTN_SMEM>>>();

    // out = attn @ Wproj + bproj  (x1, fp32 output)
    gemm_f16_kernel<<<dim3(WIDTH / 128, MQ / 128), 256, GEMM_SMEM>>>(
        ah, wph, bproj, out, nullptr, MQ, WIDTH, WIDTH, 1);
}